// round 6
// baseline (speedup 1.0000x reference)
#include <cuda_runtime.h>

// Problem constants (fixed by the reference)
#define NNODES 50000
#define MAXE   1600000
#define ETOTMAX (MAXE + NNODES)
#define HF     128      // H*F
#define FDIM   64
#define NCLS   16
#define SCAN_NBLK 49    // cdiv(NNODES, 1024)

// ---------------- scratch (device globals; no allocation allowed) -------------
__device__ float    g_h[NNODES * HF];
__device__ float    g_h2[NNODES * HF];
__device__ float    g_as[NNODES * 2];
__device__ float    g_ad[NNODES * 2];
__device__ float    g_z1[NNODES * 512];
__device__ float    g_z2[NNODES * 256];
// CSR scratch
__device__ int      g_deg[NNODES];
__device__ int      g_pos[NNODES];
__device__ int      g_off[NNODES + 1];
__device__ int      g_csr[ETOTMAX];
__device__ int      g_bsum[64];

static inline int cdiv(int a, int b) { return (a + b - 1) / b; }

// ============================ CSR build ======================================
// Self-loops are folded in analytically: deg starts at 1, pos starts at 1,
// and slot g_off[n] of each node holds the self loop (written in scan3).
__global__ void csr_zero_kernel()
{
    int i = blockIdx.x * blockDim.x + threadIdx.x;   // over NNODES/4
    int4 one = make_int4(1, 1, 1, 1);
    if (i * 4 + 3 < NNODES) {
        *reinterpret_cast<int4*>(&g_deg[i * 4]) = one;
        *reinterpret_cast<int4*>(&g_pos[i * 4]) = one;
    } else {
        for (int j = i * 4; j < NNODES; j++) { g_deg[j] = 1; g_pos[j] = 1; }
    }
}

// 4 edges per thread, vectorized when E % 4 == 0
__global__ void csr_count_kernel(const int* __restrict__ ei, int E, int vec)
{
    int i = blockIdx.x * blockDim.x + threadIdx.x;
    if (vec) {
        int base = i * 4;
        if (base + 3 < E) {
            int4 d = *reinterpret_cast<const int4*>(&ei[E + base]);
            atomicAdd(&g_deg[d.x], 1);
            atomicAdd(&g_deg[d.y], 1);
            atomicAdd(&g_deg[d.z], 1);
            atomicAdd(&g_deg[d.w], 1);
        } else {
            for (int j = base; j < E; j++) atomicAdd(&g_deg[ei[E + j]], 1);
        }
    } else {
        for (int j = i * 4; j < min(i * 4 + 4, E); j++)
            atomicAdd(&g_deg[ei[E + j]], 1);
    }
}

__global__ void csr_scan1_kernel()
{
    __shared__ int buf[1024];
    int t = threadIdx.x;
    int i = blockIdx.x * 1024 + t;
    int v = (i < NNODES) ? g_deg[i] : 0;
    buf[t] = v;
    __syncthreads();
#pragma unroll
    for (int off = 1; off < 1024; off <<= 1) {
        int tv = (t >= off) ? buf[t - off] : 0;
        __syncthreads();
        buf[t] += tv;
        __syncthreads();
    }
    if (i < NNODES) g_off[i + 1] = buf[t];
    if (t == 1023) g_bsum[blockIdx.x] = buf[t];
}

__global__ void csr_scan2_kernel()
{
    int run = 0;
#pragma unroll
    for (int b = 0; b < SCAN_NBLK; b++) {
        int v = g_bsum[b];
        g_bsum[b] = run;
        run += v;
    }
}

// add carries + write self-loop slots (start of each node's segment)
__global__ void csr_scan3_kernel()
{
    int i = blockIdx.x * blockDim.x + threadIdx.x;
    if (i == 0) { g_off[0] = 0; g_csr[0] = 0; }   // node 0 self loop at slot 0
    if (i < NNODES) {
        int v = g_off[i + 1] + g_bsum[i >> 10];
        g_off[i + 1] = v;
        if (i + 1 < NNODES) g_csr[v] = i + 1;     // self loop of node i+1
    }
}

__global__ void csr_scatter_kernel(const int* __restrict__ ei, int E, int vec)
{
    int i = blockIdx.x * blockDim.x + threadIdx.x;
    if (vec) {
        int base = i * 4;
        if (base + 3 < E) {
            int4 s = *reinterpret_cast<const int4*>(&ei[base]);
            int4 d = *reinterpret_cast<const int4*>(&ei[E + base]);
            g_csr[g_off[d.x] + atomicAdd(&g_pos[d.x], 1)] = s.x;
            g_csr[g_off[d.y] + atomicAdd(&g_pos[d.y], 1)] = s.y;
            g_csr[g_off[d.z] + atomicAdd(&g_pos[d.z], 1)] = s.z;
            g_csr[g_off[d.w] + atomicAdd(&g_pos[d.w], 1)] = s.w;
        } else {
            for (int j = base; j < E; j++) {
                int d = ei[E + j];
                g_csr[g_off[d] + atomicAdd(&g_pos[d], 1)] = ei[j];
            }
        }
    } else {
        for (int j = i * 4; j < min(i * 4 + 4, E); j++) {
            int d = ei[E + j];
            g_csr[g_off[d] + atomicAdd(&g_pos[d], 1)] = ei[j];
        }
    }
}

// ============================ tf32 helpers ===================================
__device__ __forceinline__ unsigned f2tf32(float f)
{
    unsigned r;
    asm("cvt.rna.tf32.f32 %0, %1;" : "=r"(r) : "f"(f));
    return r;
}

__device__ __forceinline__ void mma_tf32(float c[4], const unsigned a[4],
                                         unsigned b0, unsigned b1)
{
    asm volatile(
        "mma.sync.aligned.m16n8k8.row.col.f32.tf32.tf32.f32 "
        "{%0,%1,%2,%3},{%4,%5,%6,%7},{%8,%9},{%0,%1,%2,%3};"
        : "+f"(c[0]), "+f"(c[1]), "+f"(c[2]), "+f"(c[3])
        : "r"(a[0]), "r"(a[1]), "r"(a[2]), "r"(a[3]), "r"(b0), "r"(b1));
}

// ============================ pipelined tf32 GEMM ============================
// BM=BN=128, BK=16, 256 threads. Double-buffered. B stored PERMUTED in smem:
// within each 64-col warp strip, column n lives at (n%8)*8 + n/8, so the 8
// B-fragment values a lane needs (ni=0..7, fixed g) are contiguous -> 2 LDS.128.
__global__ __launch_bounds__(256) void gemm_tf32_kernel(
    const float* __restrict__ A, const float* __restrict__ B,
    const float* __restrict__ bias, float* __restrict__ C,
    int M, int Nn, int K, int doRelu)
{
    __shared__ float As[2][16][132];
    __shared__ float Bs[2][16][132];

    int tid = threadIdx.x;
    int lane = tid & 31, wid = tid >> 5;
    int wr = wid >> 1, wc = wid & 1;
    int row0 = blockIdx.y * 128, col0 = blockIdx.x * 128;
    int g = lane >> 2, tig = lane & 3;

    float acc[2][8][4];
#pragma unroll
    for (int mi = 0; mi < 2; mi++)
#pragma unroll
        for (int ni = 0; ni < 8; ni++)
#pragma unroll
            for (int q = 0; q < 4; q++) acc[mi][ni][q] = 0.f;

    int ar = tid >> 2;
    int akc = (tid & 3) * 4;
    int bkr = tid >> 5;
    int bnc = (tid & 31) * 4;

    // permuted column indices for B stores (4 consecutive n)
    int pn[4];
#pragma unroll
    for (int q = 0; q < 4; q++) {
        int n = bnc + q;
        int w = n & 63;
        pn[q] = (n >> 6) * 64 + (w & 7) * 8 + (w >> 3);
    }

    float4 ra[2], rb[2];

    auto load_tiles = [&](int k0) {
#pragma unroll
        for (int rr = 0; rr < 2; rr++) {
            int grow = row0 + ar + rr * 64;
            ra[rr] = make_float4(0.f, 0.f, 0.f, 0.f);
            if (grow < M)
                ra[rr] = *reinterpret_cast<const float4*>(&A[(long)grow * K + k0 + akc]);
        }
#pragma unroll
        for (int rr = 0; rr < 2; rr++) {
            int kr = k0 + bkr + rr * 8;
            rb[rr] = *reinterpret_cast<const float4*>(&B[(long)kr * Nn + col0 + bnc]);
        }
    };

    auto store_tiles = [&](int buf) {
#pragma unroll
        for (int rr = 0; rr < 2; rr++) {
            As[buf][akc + 0][ar + rr * 64] = __uint_as_float(f2tf32(ra[rr].x));
            As[buf][akc + 1][ar + rr * 64] = __uint_as_float(f2tf32(ra[rr].y));
            As[buf][akc + 2][ar + rr * 64] = __uint_as_float(f2tf32(ra[rr].z));
            As[buf][akc + 3][ar + rr * 64] = __uint_as_float(f2tf32(ra[rr].w));
        }
#pragma unroll
        for (int rr = 0; rr < 2; rr++) {
            int kr = bkr + rr * 8;
            Bs[buf][kr][pn[0]] = __uint_as_float(f2tf32(rb[rr].x));
            Bs[buf][kr][pn[1]] = __uint_as_float(f2tf32(rb[rr].y));
            Bs[buf][kr][pn[2]] = __uint_as_float(f2tf32(rb[rr].z));
            Bs[buf][kr][pn[3]] = __uint_as_float(f2tf32(rb[rr].w));
        }
    };

    int nk = K >> 4;
    load_tiles(0);
    store_tiles(0);
    __syncthreads();

    for (int it = 0; it < nk; it++) {
        int cur = it & 1;
        bool has_next = (it + 1 < nk);
        if (has_next) load_tiles((it + 1) << 4);

#pragma unroll
        for (int ks = 0; ks < 16; ks += 8) {
            unsigned af[2][4];
#pragma unroll
            for (int mi = 0; mi < 2; mi++) {
                int mb = wr * 32 + mi * 16 + g;
                af[mi][0] = __float_as_uint(As[cur][ks + tig][mb]);
                af[mi][1] = __float_as_uint(As[cur][ks + tig][mb + 8]);
                af[mi][2] = __float_as_uint(As[cur][ks + tig + 4][mb]);
                af[mi][3] = __float_as_uint(As[cur][ks + tig + 4][mb + 8]);
            }
            // B fragments: 8 contiguous floats per k-row (permuted layout)
            float4 b1lo = *reinterpret_cast<const float4*>(&Bs[cur][ks + tig][wc * 64 + g * 8]);
            float4 b1hi = *reinterpret_cast<const float4*>(&Bs[cur][ks + tig][wc * 64 + g * 8 + 4]);
            float4 b2lo = *reinterpret_cast<const float4*>(&Bs[cur][ks + tig + 4][wc * 64 + g * 8]);
            float4 b2hi = *reinterpret_cast<const float4*>(&Bs[cur][ks + tig + 4][wc * 64 + g * 8 + 4]);
            const float* b1 = &b1lo.x;   // b1lo.x..w, b1hi.x..w contiguous in regs
            const float* b2 = &b2lo.x;
            float bb1[8] = {b1lo.x, b1lo.y, b1lo.z, b1lo.w, b1hi.x, b1hi.y, b1hi.z, b1hi.w};
            float bb2[8] = {b2lo.x, b2lo.y, b2lo.z, b2lo.w, b2hi.x, b2hi.y, b2hi.z, b2hi.w};
            (void)b1; (void)b2;
#pragma unroll
            for (int ni = 0; ni < 8; ni++) {
                unsigned b0 = __float_as_uint(bb1[ni]);
                unsigned b1v = __float_as_uint(bb2[ni]);
                mma_tf32(acc[0][ni], af[0], b0, b1v);
                mma_tf32(acc[1][ni], af[1], b0, b1v);
            }
        }

        if (has_next) store_tiles(cur ^ 1);
        __syncthreads();
    }

#pragma unroll
    for (int mi = 0; mi < 2; mi++) {
#pragma unroll
        for (int ni = 0; ni < 8; ni++) {
            int r0 = row0 + wr * 32 + mi * 16 + g;
            int c0 = col0 + wc * 64 + ni * 8 + 2 * tig;
#pragma unroll
            for (int half = 0; half < 2; half++) {
                int gr = r0 + half * 8;
                if (gr >= M) continue;
                float v0 = acc[mi][ni][half * 2 + 0];
                float v1 = acc[mi][ni][half * 2 + 1];
                if (bias) { v0 += bias[c0]; v1 += bias[c0 + 1]; }
                if (doRelu) { v0 = fmaxf(v0, 0.f); v1 = fmaxf(v1, 0.f); }
                C[(long)gr * Nn + c0] = v0;
                C[(long)gr * Nn + c0 + 1] = v1;
            }
        }
    }
}

// ============================ tf32 GEMM, N = 16 ==============================
__global__ __launch_bounds__(256) void gemm_tf32_n16_kernel(
    const float* __restrict__ A, const float* __restrict__ B,
    const float* __restrict__ bias, float* __restrict__ C,
    int M, int K)
{
    __shared__ float As[32][132];
    __shared__ float Bs[32][20];

    int tid = threadIdx.x;
    int lane = tid & 31, wid = tid >> 5;
    int g = lane >> 2, tig = lane & 3;
    int row0 = blockIdx.x * 128;

    float acc[2][4];
#pragma unroll
    for (int ni = 0; ni < 2; ni++)
#pragma unroll
        for (int q = 0; q < 4; q++) acc[ni][q] = 0.f;

    int ar = tid >> 1;
    int akc0 = (tid & 1) * 16;
    int bk = tid >> 3;
    int bn = (tid & 7) * 2;

    for (int k0 = 0; k0 < K; k0 += 32) {
        int gr = row0 + ar;
#pragma unroll
        for (int q = 0; q < 4; q++) {
            int kc = akc0 + q * 4;
            float4 v = make_float4(0.f, 0.f, 0.f, 0.f);
            if (gr < M) v = *reinterpret_cast<const float4*>(&A[(long)gr * K + k0 + kc]);
            As[kc + 0][ar] = __uint_as_float(f2tf32(v.x));
            As[kc + 1][ar] = __uint_as_float(f2tf32(v.y));
            As[kc + 2][ar] = __uint_as_float(f2tf32(v.z));
            As[kc + 3][ar] = __uint_as_float(f2tf32(v.w));
        }
        Bs[bk][bn]     = __uint_as_float(f2tf32(B[(long)(k0 + bk) * 16 + bn]));
        Bs[bk][bn + 1] = __uint_as_float(f2tf32(B[(long)(k0 + bk) * 16 + bn + 1]));
        __syncthreads();

#pragma unroll
        for (int ks = 0; ks < 32; ks += 8) {
            int mb = wid * 16 + g;
            unsigned a[4];
            a[0] = __float_as_uint(As[ks + tig][mb]);
            a[1] = __float_as_uint(As[ks + tig][mb + 8]);
            a[2] = __float_as_uint(As[ks + tig + 4][mb]);
            a[3] = __float_as_uint(As[ks + tig + 4][mb + 8]);
#pragma unroll
            for (int ni = 0; ni < 2; ni++) {
                unsigned b0 = __float_as_uint(Bs[ks + tig][ni * 8 + g]);
                unsigned b1 = __float_as_uint(Bs[ks + tig + 4][ni * 8 + g]);
                mma_tf32(acc[ni], a, b0, b1);
            }
        }
        __syncthreads();
    }

#pragma unroll
    for (int ni = 0; ni < 2; ni++) {
        int c0 = ni * 8 + 2 * tig;
#pragma unroll
        for (int half = 0; half < 2; half++) {
            int gr = row0 + wid * 16 + g + half * 8;
            if (gr >= M) continue;
            C[(long)gr * 16 + c0]     = acc[ni][half * 2 + 0] + bias[c0];
            C[(long)gr * 16 + c0 + 1] = acc[ni][half * 2 + 1] + bias[c0 + 1];
        }
    }
}

// ---------------- per-node alpha_src/alpha_dst --------------------------------
__global__ void alpha_kernel(const float* __restrict__ asrc,
                             const float* __restrict__ adst)
{
    int w = (blockIdx.x * blockDim.x + threadIdx.x) >> 5;
    int lane = threadIdx.x & 31;
    if (w >= NNODES) return;
    float4 hv = reinterpret_cast<const float4*>(&g_h[(long)w * HF])[lane];
    float4 sa = reinterpret_cast<const float4*>(asrc)[lane];
    float4 da = reinterpret_cast<const float4*>(adst)[lane];
    float s = hv.x * sa.x + hv.y * sa.y + hv.z * sa.z + hv.w * sa.w;
    float d = hv.x * da.x + hv.y * da.y + hv.z * da.z + hv.w * da.w;
#pragma unroll
    for (int off = 8; off; off >>= 1) {
        s += __shfl_down_sync(0xffffffffu, s, off, 16);
        d += __shfl_down_sync(0xffffffffu, d, off, 16);
    }
    if ((lane & 15) == 0) {
        int hh = lane >> 4;
        g_as[w * 2 + hh] = s;
        g_ad[w * 2 + hh] = d;
    }
}

// ---------------- fused softmax + aggregation (warp per dst node) -------------
__global__ void agg_kernel(const float* __restrict__ bias, float* __restrict__ dst)
{
    int n = (blockIdx.x * blockDim.x + threadIdx.x) >> 5;
    int lane = threadIdx.x & 31;
    if (n >= NNODES) return;
    int beg = g_off[n], end = g_off[n + 1];
    float ad0 = g_ad[n * 2 + 0], ad1 = g_ad[n * 2 + 1];
    int head1 = lane >= 16;

    float4 acc = make_float4(0.f, 0.f, 0.f, 0.f);
    float s0 = 0.f, s1 = 0.f;

    for (int base = beg; base < end; base += 32) {
        int cnt = min(32, end - base);
        int sl = 0; float ex0 = 0.f, ex1 = 0.f;
        if (lane < cnt) {
            sl = g_csr[base + lane];
            float2 a = *reinterpret_cast<const float2*>(&g_as[sl * 2]);
            float e0 = a.x + ad0; e0 = fmaxf(e0, 0.2f * e0);
            float e1 = a.y + ad1; e1 = fmaxf(e1, 0.2f * e1);
            ex0 = __expf(e0);
            ex1 = __expf(e1);
        }
        for (int t = 0; t < cnt; t++) {
            int s    = __shfl_sync(0xffffffffu, sl, t);
            float w0 = __shfl_sync(0xffffffffu, ex0, t);
            float w1 = __shfl_sync(0xffffffffu, ex1, t);
            s0 += w0; s1 += w1;
            float4 hv = reinterpret_cast<const float4*>(&g_h[(long)s * HF])[lane];
            float w = head1 ? w1 : w0;
            acc.x = fmaf(hv.x, w, acc.x);
            acc.y = fmaf(hv.y, w, acc.y);
            acc.z = fmaf(hv.z, w, acc.z);
            acc.w = fmaf(hv.w, w, acc.w);
        }
    }
    float r = head1 ? (1.f / (s1 + 1e-16f)) : (1.f / (s0 + 1e-16f));
    float4 b = reinterpret_cast<const float4*>(bias)[lane];
    float4 o;
    o.x = fmaxf(fmaf(acc.x, r, b.x), 0.f);
    o.y = fmaxf(fmaf(acc.y, r, b.y), 0.f);
    o.z = fmaxf(fmaf(acc.z, r, b.z), 0.f);
    o.w = fmaxf(fmaf(acc.w, r, b.w), 0.f);
    reinterpret_cast<float4*>(&dst[(long)n * HF])[lane] = o;
}

// ---------------- launch ------------------------------------------------------
extern "C" void kernel_launch(void* const* d_in, const int* in_sizes, int n_in,
                              void* d_out, int out_size)
{
    const float* x      = (const float*)d_in[0];
    const int*   ei     = (const int*)  d_in[1];
    const float* W1     = (const float*)d_in[2];
    const float* a_src1 = (const float*)d_in[3];
    const float* a_dst1 = (const float*)d_in[4];
    const float* b1     = (const float*)d_in[5];
    const float* W2     = (const float*)d_in[6];
    const float* a_src2 = (const float*)d_in[7];
    const float* a_dst2 = (const float*)d_in[8];
    const float* b2     = (const float*)d_in[9];
    const float* lw1    = (const float*)d_in[10];
    const float* lb1    = (const float*)d_in[11];
    const float* lw2    = (const float*)d_in[12];
    const float* lb2    = (const float*)d_in[13];
    const float* lw3    = (const float*)d_in[14];
    const float* lb3    = (const float*)d_in[15];

    int E = in_sizes[1] / 2;
    int vec = ((E & 3) == 0) ? 1 : 0;

    float* out    = (float*)d_out;
    float* emb    = out;                       // [N, 128]
    float* logits = out + (long)NNODES * HF;   // [N, 16]

    float *p_h, *p_h2, *p_z1, *p_z2;
    cudaGetSymbolAddress((void**)&p_h,  g_h);
    cudaGetSymbolAddress((void**)&p_h2, g_h2);
    cudaGetSymbolAddress((void**)&p_z1, g_z1);
    cudaGetSymbolAddress((void**)&p_z2, g_z2);

    int e4Blocks    = cdiv(cdiv(E, 4), 256);
    int nodeBlocks  = cdiv(NNODES, 256);
    int node4Blocks = cdiv(cdiv(NNODES, 4), 256);
    int warpNodeBlk = cdiv(NNODES, 8);

    // ---------------- CSR build ----------------
    csr_zero_kernel<<<node4Blocks, 256>>>();
    csr_count_kernel<<<e4Blocks, 256>>>(ei, E, vec);
    csr_scan1_kernel<<<SCAN_NBLK, 1024>>>();
    csr_scan2_kernel<<<1, 1>>>();
    csr_scan3_kernel<<<nodeBlocks, 256>>>();
    csr_scatter_kernel<<<e4Blocks, 256>>>(ei, E, vec);

    // ---------------- GAT layer 1 ----------------
    {
        dim3 grid(HF / 128, cdiv(NNODES, 128));
        gemm_tf32_kernel<<<grid, 256>>>(x, W1, nullptr, p_h, NNODES, HF, FDIM, 0);
    }
    alpha_kernel<<<warpNodeBlk, 256>>>(a_src1, a_dst1);
    agg_kernel<<<warpNodeBlk, 256>>>(b1, p_h2);

    // ---------------- GAT layer 2 ----------------
    {
        dim3 grid(HF / 128, cdiv(NNODES, 128));
        gemm_tf32_kernel<<<grid, 256>>>(p_h2, W2, nullptr, p_h, NNODES, HF, HF, 0);
    }
    alpha_kernel<<<warpNodeBlk, 256>>>(a_src2, a_dst2);
    agg_kernel<<<warpNodeBlk, 256>>>(b2, emb);

    // ---------------- MLP head ----------------
    {
        dim3 grid(512 / 128, cdiv(NNODES, 128));
        gemm_tf32_kernel<<<grid, 256>>>(emb, lw1, lb1, p_z1, NNODES, 512, HF, 1);
    }
    {
        dim3 grid(256 / 128, cdiv(NNODES, 128));
        gemm_tf32_kernel<<<grid, 256>>>(p_z1, lw2, lb2, p_z2, NNODES, 256, 512, 1);
    }
    gemm_tf32_n16_kernel<<<cdiv(NNODES, 128), 256>>>(p_z2, lw3, lb3, logits, NNODES, 256);
}

// round 8
// speedup vs baseline: 1.0422x; 1.0422x over previous
#include <cuda_runtime.h>

// Problem constants (fixed by the reference)
#define NNODES 50000
#define MAXE   1600000
#define ETOTMAX (MAXE + NNODES)
#define HF     128      // H*F
#define FDIM   64
#define NCLS   16
#define SCAN_NBLK 49    // cdiv(NNODES, 1024)

// ---------------- scratch (device globals; no allocation allowed) -------------
__device__ float    g_h[NNODES * HF];
__device__ float    g_h2[NNODES * HF];
__device__ float    g_as[NNODES * 2];
__device__ float    g_ad[NNODES * 2];
__device__ float    g_z1[NNODES * 512];
__device__ float    g_z2[NNODES * 256];
// CSR scratch
__device__ int      g_deg[NNODES];
__device__ int      g_pos[NNODES];
__device__ int      g_off[NNODES + 1];
__device__ int      g_csr[ETOTMAX];
__device__ int      g_bsum[64];

static inline int cdiv(int a, int b) { return (a + b - 1) / b; }

// ============================ CSR build ======================================
// Self-loops folded analytically: deg/pos start at 1; slot g_off[n] of each
// node holds its self loop (written in scan_fix).
__global__ void csr_zero_kernel()
{
    int i = blockIdx.x * blockDim.x + threadIdx.x;
    int4 one = make_int4(1, 1, 1, 1);
    if (i * 4 + 3 < NNODES) {
        *reinterpret_cast<int4*>(&g_deg[i * 4]) = one;
        *reinterpret_cast<int4*>(&g_pos[i * 4]) = one;
    } else {
        for (int j = i * 4; j < NNODES; j++) { g_deg[j] = 1; g_pos[j] = 1; }
    }
}

// one edge per thread (max parallelism hides atomic latency)
__global__ void csr_count_kernel(const int* __restrict__ ei, int E)
{
    int i = blockIdx.x * blockDim.x + threadIdx.x;
    if (i >= E) return;
    atomicAdd(&g_deg[ei[E + i]], 1);
}

__global__ void csr_scan1_kernel()
{
    __shared__ int buf[1024];
    int t = threadIdx.x;
    int i = blockIdx.x * 1024 + t;
    int v = (i < NNODES) ? g_deg[i] : 0;
    buf[t] = v;
    __syncthreads();
#pragma unroll
    for (int off = 1; off < 1024; off <<= 1) {
        int tv = (t >= off) ? buf[t - off] : 0;
        __syncthreads();
        buf[t] += tv;
        __syncthreads();
    }
    if (i < NNODES) g_off[i + 1] = buf[t];
    if (t == 1023) g_bsum[blockIdx.x] = buf[t];
}

// carry-add with in-block scan of the 49 block sums + self-loop slot writes
__global__ void csr_scan_fix_kernel()
{
    __shared__ int carry[SCAN_NBLK];
    int t = threadIdx.x;
    if (t < SCAN_NBLK) carry[t] = g_bsum[t];
    __syncthreads();
    if (t == 0) {
        int run = 0;
#pragma unroll
        for (int b = 0; b < SCAN_NBLK; b++) { int v = carry[b]; carry[b] = run; run += v; }
    }
    __syncthreads();
    int i = blockIdx.x * blockDim.x + t;
    if (i == 0) { g_off[0] = 0; g_csr[0] = 0; }   // node 0 self loop
    if (i < NNODES) {
        int v = g_off[i + 1] + carry[i >> 10];
        g_off[i + 1] = v;
        if (i + 1 < NNODES) g_csr[v] = i + 1;     // self loop of node i+1
    }
}

__global__ void csr_scatter_kernel(const int* __restrict__ ei, int E)
{
    int i = blockIdx.x * blockDim.x + threadIdx.x;
    if (i >= E) return;
    int s = ei[i], d = ei[E + i];
    int idx = g_off[d] + atomicAdd(&g_pos[d], 1);
    g_csr[idx] = s;
}

// ============================ tf32 helpers ===================================
__device__ __forceinline__ unsigned f2tf32(float f)
{
    unsigned r;
    asm("cvt.rna.tf32.f32 %0, %1;" : "=r"(r) : "f"(f));
    return r;
}

__device__ __forceinline__ void mma_tf32(float c[4], const unsigned a[4],
                                         unsigned b0, unsigned b1)
{
    asm volatile(
        "mma.sync.aligned.m16n8k8.row.col.f32.tf32.tf32.f32 "
        "{%0,%1,%2,%3},{%4,%5,%6,%7},{%8,%9},{%0,%1,%2,%3};"
        : "+f"(c[0]), "+f"(c[1]), "+f"(c[2]), "+f"(c[3])
        : "r"(a[0]), "r"(a[1]), "r"(a[2]), "r"(a[3]), "r"(b0), "r"(b1));
}

// ============================ pipelined tf32 GEMM (R5 version) ===============
__global__ __launch_bounds__(256) void gemm_tf32_kernel(
    const float* __restrict__ A, const float* __restrict__ B,
    const float* __restrict__ bias, float* __restrict__ C,
    int M, int Nn, int K, int doRelu)
{
    __shared__ float As[2][16][132];
    __shared__ float Bs[2][16][132];

    int tid = threadIdx.x;
    int lane = tid & 31, wid = tid >> 5;
    int wr = wid >> 1, wc = wid & 1;
    int row0 = blockIdx.y * 128, col0 = blockIdx.x * 128;
    int g = lane >> 2, tig = lane & 3;

    float acc[2][8][4];
#pragma unroll
    for (int mi = 0; mi < 2; mi++)
#pragma unroll
        for (int ni = 0; ni < 8; ni++)
#pragma unroll
            for (int q = 0; q < 4; q++) acc[mi][ni][q] = 0.f;

    int ar = tid >> 2;
    int akc = (tid & 3) * 4;
    int bkr = tid >> 5;
    int bnc = (tid & 31) * 4;

    float4 ra[2], rb[2];

    auto load_tiles = [&](int k0) {
#pragma unroll
        for (int rr = 0; rr < 2; rr++) {
            int grow = row0 + ar + rr * 64;
            ra[rr] = make_float4(0.f, 0.f, 0.f, 0.f);
            if (grow < M)
                ra[rr] = *reinterpret_cast<const float4*>(&A[(long)grow * K + k0 + akc]);
        }
#pragma unroll
        for (int rr = 0; rr < 2; rr++) {
            int kr = k0 + bkr + rr * 8;
            rb[rr] = *reinterpret_cast<const float4*>(&B[(long)kr * Nn + col0 + bnc]);
        }
    };

    auto store_tiles = [&](int buf) {
#pragma unroll
        for (int rr = 0; rr < 2; rr++) {
            As[buf][akc + 0][ar + rr * 64] = __uint_as_float(f2tf32(ra[rr].x));
            As[buf][akc + 1][ar + rr * 64] = __uint_as_float(f2tf32(ra[rr].y));
            As[buf][akc + 2][ar + rr * 64] = __uint_as_float(f2tf32(ra[rr].z));
            As[buf][akc + 3][ar + rr * 64] = __uint_as_float(f2tf32(ra[rr].w));
        }
#pragma unroll
        for (int rr = 0; rr < 2; rr++) {
            float4 t;
            t.x = __uint_as_float(f2tf32(rb[rr].x));
            t.y = __uint_as_float(f2tf32(rb[rr].y));
            t.z = __uint_as_float(f2tf32(rb[rr].z));
            t.w = __uint_as_float(f2tf32(rb[rr].w));
            *reinterpret_cast<float4*>(&Bs[buf][bkr + rr * 8][bnc]) = t;
        }
    };

    int nk = K >> 4;
    load_tiles(0);
    store_tiles(0);
    __syncthreads();

    for (int it = 0; it < nk; it++) {
        int cur = it & 1;
        bool has_next = (it + 1 < nk);
        if (has_next) load_tiles((it + 1) << 4);

#pragma unroll
        for (int ks = 0; ks < 16; ks += 8) {
            unsigned af[2][4];
#pragma unroll
            for (int mi = 0; mi < 2; mi++) {
                int mb = wr * 32 + mi * 16 + g;
                af[mi][0] = __float_as_uint(As[cur][ks + tig][mb]);
                af[mi][1] = __float_as_uint(As[cur][ks + tig][mb + 8]);
                af[mi][2] = __float_as_uint(As[cur][ks + tig + 4][mb]);
                af[mi][3] = __float_as_uint(As[cur][ks + tig + 4][mb + 8]);
            }
#pragma unroll
            for (int ni = 0; ni < 8; ni++) {
                int nb = wc * 64 + ni * 8 + g;
                unsigned b0 = __float_as_uint(Bs[cur][ks + tig][nb]);
                unsigned b1 = __float_as_uint(Bs[cur][ks + tig + 4][nb]);
                mma_tf32(acc[0][ni], af[0], b0, b1);
                mma_tf32(acc[1][ni], af[1], b0, b1);
            }
        }

        if (has_next) store_tiles(cur ^ 1);
        __syncthreads();
    }

#pragma unroll
    for (int mi = 0; mi < 2; mi++) {
#pragma unroll
        for (int ni = 0; ni < 8; ni++) {
            int r0 = row0 + wr * 32 + mi * 16 + g;
            int c0 = col0 + wc * 64 + ni * 8 + 2 * tig;
#pragma unroll
            for (int half = 0; half < 2; half++) {
                int gr = r0 + half * 8;
                if (gr >= M) continue;
                float v0 = acc[mi][ni][half * 2 + 0];
                float v1 = acc[mi][ni][half * 2 + 1];
                if (bias) { v0 += bias[c0]; v1 += bias[c0 + 1]; }
                if (doRelu) { v0 = fmaxf(v0, 0.f); v1 = fmaxf(v1, 0.f); }
                C[(long)gr * Nn + c0] = v0;
                C[(long)gr * Nn + c0 + 1] = v1;
            }
        }
    }
}

// ============================ tf32 GEMM, N = 16 ==============================
__global__ __launch_bounds__(256) void gemm_tf32_n16_kernel(
    const float* __restrict__ A, const float* __restrict__ B,
    const float* __restrict__ bias, float* __restrict__ C,
    int M, int K)
{
    __shared__ float As[32][132];
    __shared__ float Bs[32][20];

    int tid = threadIdx.x;
    int lane = tid & 31, wid = tid >> 5;
    int g = lane >> 2, tig = lane & 3;
    int row0 = blockIdx.x * 128;

    float acc[2][4];
#pragma unroll
    for (int ni = 0; ni < 2; ni++)
#pragma unroll
        for (int q = 0; q < 4; q++) acc[ni][q] = 0.f;

    int ar = tid >> 1;
    int akc0 = (tid & 1) * 16;
    int bk = tid >> 3;
    int bn = (tid & 7) * 2;

    for (int k0 = 0; k0 < K; k0 += 32) {
        int gr = row0 + ar;
#pragma unroll
        for (int q = 0; q < 4; q++) {
            int kc = akc0 + q * 4;
            float4 v = make_float4(0.f, 0.f, 0.f, 0.f);
            if (gr < M) v = *reinterpret_cast<const float4*>(&A[(long)gr * K + k0 + kc]);
            As[kc + 0][ar] = __uint_as_float(f2tf32(v.x));
            As[kc + 1][ar] = __uint_as_float(f2tf32(v.y));
            As[kc + 2][ar] = __uint_as_float(f2tf32(v.z));
            As[kc + 3][ar] = __uint_as_float(f2tf32(v.w));
        }
        Bs[bk][bn]     = __uint_as_float(f2tf32(B[(long)(k0 + bk) * 16 + bn]));
        Bs[bk][bn + 1] = __uint_as_float(f2tf32(B[(long)(k0 + bk) * 16 + bn + 1]));
        __syncthreads();

#pragma unroll
        for (int ks = 0; ks < 32; ks += 8) {
            int mb = wid * 16 + g;
            unsigned a[4];
            a[0] = __float_as_uint(As[ks + tig][mb]);
            a[1] = __float_as_uint(As[ks + tig][mb + 8]);
            a[2] = __float_as_uint(As[ks + tig + 4][mb]);
            a[3] = __float_as_uint(As[ks + tig + 4][mb + 8]);
#pragma unroll
            for (int ni = 0; ni < 2; ni++) {
                unsigned b0 = __float_as_uint(Bs[ks + tig][ni * 8 + g]);
                unsigned b1 = __float_as_uint(Bs[ks + tig + 4][ni * 8 + g]);
                mma_tf32(acc[ni], a, b0, b1);
            }
        }
        __syncthreads();
    }

#pragma unroll
    for (int ni = 0; ni < 2; ni++) {
        int c0 = ni * 8 + 2 * tig;
#pragma unroll
        for (int half = 0; half < 2; half++) {
            int gr = row0 + wid * 16 + g + half * 8;
            if (gr >= M) continue;
            C[(long)gr * 16 + c0]     = acc[ni][half * 2 + 0] + bias[c0];
            C[(long)gr * 16 + c0 + 1] = acc[ni][half * 2 + 1] + bias[c0 + 1];
        }
    }
}

// ---------------- per-node alpha_src/alpha_dst --------------------------------
__global__ void alpha_kernel(const float* __restrict__ asrc,
                             const float* __restrict__ adst)
{
    int w = (blockIdx.x * blockDim.x + threadIdx.x) >> 5;
    int lane = threadIdx.x & 31;
    if (w >= NNODES) return;
    float4 hv = reinterpret_cast<const float4*>(&g_h[(long)w * HF])[lane];
    float4 sa = reinterpret_cast<const float4*>(asrc)[lane];
    float4 da = reinterpret_cast<const float4*>(adst)[lane];
    float s = hv.x * sa.x + hv.y * sa.y + hv.z * sa.z + hv.w * sa.w;
    float d = hv.x * da.x + hv.y * da.y + hv.z * da.z + hv.w * da.w;
#pragma unroll
    for (int off = 8; off; off >>= 1) {
        s += __shfl_down_sync(0xffffffffu, s, off, 16);
        d += __shfl_down_sync(0xffffffffu, d, off, 16);
    }
    if ((lane & 15) == 0) {
        int hh = lane >> 4;
        g_as[w * 2 + hh] = s;
        g_ad[w * 2 + hh] = d;
    }
}

// ---------------- fused softmax + aggregation (warp per dst node) -------------
__global__ void agg_kernel(const float* __restrict__ bias, float* __restrict__ dst)
{
    int n = (blockIdx.x * blockDim.x + threadIdx.x) >> 5;
    int lane = threadIdx.x & 31;
    if (n >= NNODES) return;
    int beg = g_off[n], end = g_off[n + 1];
    float ad0 = g_ad[n * 2 + 0], ad1 = g_ad[n * 2 + 1];
    int head1 = lane >= 16;

    float4 acc = make_float4(0.f, 0.f, 0.f, 0.f);
    float s0 = 0.f, s1 = 0.f;

    for (int base = beg; base < end; base += 32) {
        int cnt = min(32, end - base);
        int sl = 0; float ex0 = 0.f, ex1 = 0.f;
        if (lane < cnt) {
            sl = g_csr[base + lane];
            float2 a = *reinterpret_cast<const float2*>(&g_as[sl * 2]);
            float e0 = a.x + ad0; e0 = fmaxf(e0, 0.2f * e0);
            float e1 = a.y + ad1; e1 = fmaxf(e1, 0.2f * e1);
            ex0 = __expf(e0);
            ex1 = __expf(e1);
        }
        for (int t = 0; t < cnt; t++) {
            int s    = __shfl_sync(0xffffffffu, sl, t);
            float w0 = __shfl_sync(0xffffffffu, ex0, t);
            float w1 = __shfl_sync(0xffffffffu, ex1, t);
            s0 += w0; s1 += w1;
            float4 hv = reinterpret_cast<const float4*>(&g_h[(long)s * HF])[lane];
            float w = head1 ? w1 : w0;
            acc.x = fmaf(hv.x, w, acc.x);
            acc.y = fmaf(hv.y, w, acc.y);
            acc.z = fmaf(hv.z, w, acc.z);
            acc.w = fmaf(hv.w, w, acc.w);
        }
    }
    float r = head1 ? (1.f / (s1 + 1e-16f)) : (1.f / (s0 + 1e-16f));
    float4 b = reinterpret_cast<const float4*>(bias)[lane];
    float4 o;
    o.x = fmaxf(fmaf(acc.x, r, b.x), 0.f);
    o.y = fmaxf(fmaf(acc.y, r, b.y), 0.f);
    o.z = fmaxf(fmaf(acc.z, r, b.z), 0.f);
    o.w = fmaxf(fmaf(acc.w, r, b.w), 0.f);
    reinterpret_cast<float4*>(&dst[(long)n * HF])[lane] = o;
}

// ---------------- launch ------------------------------------------------------
extern "C" void kernel_launch(void* const* d_in, const int* in_sizes, int n_in,
                              void* d_out, int out_size)
{
    const float* x      = (const float*)d_in[0];
    const int*   ei     = (const int*)  d_in[1];
    const float* W1     = (const float*)d_in[2];
    const float* a_src1 = (const float*)d_in[3];
    const float* a_dst1 = (const float*)d_in[4];
    const float* b1     = (const float*)d_in[5];
    const float* W2     = (const float*)d_in[6];
    const float* a_src2 = (const float*)d_in[7];
    const float* a_dst2 = (const float*)d_in[8];
    const float* b2     = (const float*)d_in[9];
    const float* lw1    = (const float*)d_in[10];
    const float* lb1    = (const float*)d_in[11];
    const float* lw2    = (const float*)d_in[12];
    const float* lb2    = (const float*)d_in[13];
    const float* lw3    = (const float*)d_in[14];
    const float* lb3    = (const float*)d_in[15];

    int E = in_sizes[1] / 2;

    float* out    = (float*)d_out;
    float* emb    = out;                       // [N, 128]
    float* logits = out + (long)NNODES * HF;   // [N, 16]

    float *p_h, *p_h2, *p_z1, *p_z2;
    cudaGetSymbolAddress((void**)&p_h,  g_h);
    cudaGetSymbolAddress((void**)&p_h2, g_h2);
    cudaGetSymbolAddress((void**)&p_z1, g_z1);
    cudaGetSymbolAddress((void**)&p_z2, g_z2);

    int edgeBlocks  = cdiv(E, 256);
    int nodeBlocks  = cdiv(NNODES, 256);
    int node4Blocks = cdiv(cdiv(NNODES, 4), 256);
    int warpNodeBlk = cdiv(NNODES, 8);

    // ---------------- CSR build ----------------
    csr_zero_kernel<<<node4Blocks, 256>>>();
    csr_count_kernel<<<edgeBlocks, 256>>>(ei, E);
    csr_scan1_kernel<<<SCAN_NBLK, 1024>>>();
    csr_scan_fix_kernel<<<nodeBlocks, 256>>>();
    csr_scatter_kernel<<<edgeBlocks, 256>>>(ei, E);

    // ---------------- GAT layer 1 ----------------
    {
        dim3 grid(HF / 128, cdiv(NNODES, 128));
        gemm_tf32_kernel<<<grid, 256>>>(x, W1, nullptr, p_h, NNODES, HF, FDIM, 0);
    }
    alpha_kernel<<<warpNodeBlk, 256>>>(a_src1, a_dst1);
    agg_kernel<<<warpNodeBlk, 256>>>(b1, p_h2);

    // ---------------- GAT layer 2 ----------------
    {
        dim3 grid(HF / 128, cdiv(NNODES, 128));
        gemm_tf32_kernel<<<grid, 256>>>(p_h2, W2, nullptr, p_h, NNODES, HF, HF, 0);
    }
    alpha_kernel<<<warpNodeBlk, 256>>>(a_src2, a_dst2);
    agg_kernel<<<warpNodeBlk, 256>>>(b2, emb);

    // ---------------- MLP head ----------------
    {
        dim3 grid(512 / 128, cdiv(NNODES, 128));
        gemm_tf32_kernel<<<grid, 256>>>(emb, lw1, lb1, p_z1, NNODES, 512, HF, 1);
    }
    {
        dim3 grid(256 / 128, cdiv(NNODES, 128));
        gemm_tf32_kernel<<<grid, 256>>>(p_z1, lw2, lb2, p_z2, NNODES, 256, 512, 1);
    }
    gemm_tf32_n16_kernel<<<cdiv(NNODES, 128), 256>>>(p_z2, lw3, lb3, logits, NNODES, 256);
}

// round 9
// speedup vs baseline: 1.0628x; 1.0198x over previous
#include <cuda_runtime.h>
#include <cuda_bf16.h>

// Problem constants (fixed by the reference)
#define NNODES 50000
#define MAXE   1600000
#define ETOTMAX (MAXE + NNODES)
#define HF     128      // H*F
#define FDIM   64
#define NCLS   16
#define SCAN_NBLK 49    // cdiv(NNODES, 1024)

// ---------------- scratch (device globals; no allocation allowed) -------------
__device__ float         g_h[NNODES * HF];
__device__ __nv_bfloat16 g_hb[NNODES * HF];   // bf16 mirror of g_h for agg gathers
__device__ float         g_h2[NNODES * HF];
__device__ float         g_as[NNODES * 2];
__device__ float         g_ad[NNODES * 2];
__device__ float         g_z1[NNODES * 512];
__device__ float         g_z2[NNODES * 256];
// CSR scratch
__device__ int           g_deg[NNODES];
__device__ int           g_pos[NNODES];
__device__ int           g_off[NNODES + 1];
__device__ int           g_csr[ETOTMAX];
__device__ int           g_bsum[64];

static inline int cdiv(int a, int b) { return (a + b - 1) / b; }

// ============================ CSR build ======================================
__global__ void csr_zero_kernel()
{
    int i = blockIdx.x * blockDim.x + threadIdx.x;
    int4 one = make_int4(1, 1, 1, 1);
    if (i * 4 + 3 < NNODES) {
        *reinterpret_cast<int4*>(&g_deg[i * 4]) = one;
        *reinterpret_cast<int4*>(&g_pos[i * 4]) = one;
    } else {
        for (int j = i * 4; j < NNODES; j++) { g_deg[j] = 1; g_pos[j] = 1; }
    }
}

__global__ void csr_count_kernel(const int* __restrict__ ei, int E)
{
    int i = blockIdx.x * blockDim.x + threadIdx.x;
    if (i >= E) return;
    atomicAdd(&g_deg[ei[E + i]], 1);
}

__global__ void csr_scan1_kernel()
{
    __shared__ int buf[1024];
    int t = threadIdx.x;
    int i = blockIdx.x * 1024 + t;
    int v = (i < NNODES) ? g_deg[i] : 0;
    buf[t] = v;
    __syncthreads();
#pragma unroll
    for (int off = 1; off < 1024; off <<= 1) {
        int tv = (t >= off) ? buf[t - off] : 0;
        __syncthreads();
        buf[t] += tv;
        __syncthreads();
    }
    if (i < NNODES) g_off[i + 1] = buf[t];
    if (t == 1023) g_bsum[blockIdx.x] = buf[t];
}

__global__ void csr_scan_fix_kernel()
{
    __shared__ int carry[SCAN_NBLK];
    int t = threadIdx.x;
    if (t < SCAN_NBLK) carry[t] = g_bsum[t];
    __syncthreads();
    if (t == 0) {
        int run = 0;
#pragma unroll
        for (int b = 0; b < SCAN_NBLK; b++) { int v = carry[b]; carry[b] = run; run += v; }
    }
    __syncthreads();
    int i = blockIdx.x * blockDim.x + t;
    if (i == 0) { g_off[0] = 0; g_csr[0] = 0; }
    if (i < NNODES) {
        int v = g_off[i + 1] + carry[i >> 10];
        g_off[i + 1] = v;
        if (i + 1 < NNODES) g_csr[v] = i + 1;
    }
}

__global__ void csr_scatter_kernel(const int* __restrict__ ei, int E)
{
    int i = blockIdx.x * blockDim.x + threadIdx.x;
    if (i >= E) return;
    int s = ei[i], d = ei[E + i];
    int idx = g_off[d] + atomicAdd(&g_pos[d], 1);
    g_csr[idx] = s;
}

// ============================ tf32 helpers ===================================
__device__ __forceinline__ unsigned f2tf32(float f)
{
    unsigned r;
    asm("cvt.rna.tf32.f32 %0, %1;" : "=r"(r) : "f"(f));
    return r;
}

__device__ __forceinline__ void mma_tf32(float c[4], const unsigned a[4],
                                         unsigned b0, unsigned b1)
{
    asm volatile(
        "mma.sync.aligned.m16n8k8.row.col.f32.tf32.tf32.f32 "
        "{%0,%1,%2,%3},{%4,%5,%6,%7},{%8,%9},{%0,%1,%2,%3};"
        : "+f"(c[0]), "+f"(c[1]), "+f"(c[2]), "+f"(c[3])
        : "r"(a[0]), "r"(a[1]), "r"(a[2]), "r"(a[3]), "r"(b0), "r"(b1));
}

// ============================ pipelined tf32 GEMM ============================
// Optionally writes a bf16 mirror (Cb != nullptr, requires Nn == HF layout use)
__global__ __launch_bounds__(256) void gemm_tf32_kernel(
    const float* __restrict__ A, const float* __restrict__ B,
    const float* __restrict__ bias, float* __restrict__ C,
    __nv_bfloat16* __restrict__ Cb,
    int M, int Nn, int K, int doRelu)
{
    __shared__ float As[2][16][132];
    __shared__ float Bs[2][16][132];

    int tid = threadIdx.x;
    int lane = tid & 31, wid = tid >> 5;
    int wr = wid >> 1, wc = wid & 1;
    int row0 = blockIdx.y * 128, col0 = blockIdx.x * 128;
    int g = lane >> 2, tig = lane & 3;

    float acc[2][8][4];
#pragma unroll
    for (int mi = 0; mi < 2; mi++)
#pragma unroll
        for (int ni = 0; ni < 8; ni++)
#pragma unroll
            for (int q = 0; q < 4; q++) acc[mi][ni][q] = 0.f;

    int ar = tid >> 2;
    int akc = (tid & 3) * 4;
    int bkr = tid >> 5;
    int bnc = (tid & 31) * 4;

    float4 ra[2], rb[2];

    auto load_tiles = [&](int k0) {
#pragma unroll
        for (int rr = 0; rr < 2; rr++) {
            int grow = row0 + ar + rr * 64;
            ra[rr] = make_float4(0.f, 0.f, 0.f, 0.f);
            if (grow < M)
                ra[rr] = *reinterpret_cast<const float4*>(&A[(long)grow * K + k0 + akc]);
        }
#pragma unroll
        for (int rr = 0; rr < 2; rr++) {
            int kr = k0 + bkr + rr * 8;
            rb[rr] = *reinterpret_cast<const float4*>(&B[(long)kr * Nn + col0 + bnc]);
        }
    };

    auto store_tiles = [&](int buf) {
#pragma unroll
        for (int rr = 0; rr < 2; rr++) {
            As[buf][akc + 0][ar + rr * 64] = __uint_as_float(f2tf32(ra[rr].x));
            As[buf][akc + 1][ar + rr * 64] = __uint_as_float(f2tf32(ra[rr].y));
            As[buf][akc + 2][ar + rr * 64] = __uint_as_float(f2tf32(ra[rr].z));
            As[buf][akc + 3][ar + rr * 64] = __uint_as_float(f2tf32(ra[rr].w));
        }
#pragma unroll
        for (int rr = 0; rr < 2; rr++) {
            float4 t;
            t.x = __uint_as_float(f2tf32(rb[rr].x));
            t.y = __uint_as_float(f2tf32(rb[rr].y));
            t.z = __uint_as_float(f2tf32(rb[rr].z));
            t.w = __uint_as_float(f2tf32(rb[rr].w));
            *reinterpret_cast<float4*>(&Bs[buf][bkr + rr * 8][bnc]) = t;
        }
    };

    int nk = K >> 4;
    load_tiles(0);
    store_tiles(0);
    __syncthreads();

    for (int it = 0; it < nk; it++) {
        int cur = it & 1;
        bool has_next = (it + 1 < nk);
        if (has_next) load_tiles((it + 1) << 4);

#pragma unroll
        for (int ks = 0; ks < 16; ks += 8) {
            unsigned af[2][4];
#pragma unroll
            for (int mi = 0; mi < 2; mi++) {
                int mb = wr * 32 + mi * 16 + g;
                af[mi][0] = __float_as_uint(As[cur][ks + tig][mb]);
                af[mi][1] = __float_as_uint(As[cur][ks + tig][mb + 8]);
                af[mi][2] = __float_as_uint(As[cur][ks + tig + 4][mb]);
                af[mi][3] = __float_as_uint(As[cur][ks + tig + 4][mb + 8]);
            }
#pragma unroll
            for (int ni = 0; ni < 8; ni++) {
                int nb = wc * 64 + ni * 8 + g;
                unsigned b0 = __float_as_uint(Bs[cur][ks + tig][nb]);
                unsigned b1 = __float_as_uint(Bs[cur][ks + tig + 4][nb]);
                mma_tf32(acc[0][ni], af[0], b0, b1);
                mma_tf32(acc[1][ni], af[1], b0, b1);
            }
        }

        if (has_next) store_tiles(cur ^ 1);
        __syncthreads();
    }

#pragma unroll
    for (int mi = 0; mi < 2; mi++) {
#pragma unroll
        for (int ni = 0; ni < 8; ni++) {
            int r0 = row0 + wr * 32 + mi * 16 + g;
            int c0 = col0 + wc * 64 + ni * 8 + 2 * tig;
#pragma unroll
            for (int half = 0; half < 2; half++) {
                int gr = r0 + half * 8;
                if (gr >= M) continue;
                float v0 = acc[mi][ni][half * 2 + 0];
                float v1 = acc[mi][ni][half * 2 + 1];
                if (bias) { v0 += bias[c0]; v1 += bias[c0 + 1]; }
                if (doRelu) { v0 = fmaxf(v0, 0.f); v1 = fmaxf(v1, 0.f); }
                C[(long)gr * Nn + c0] = v0;
                C[(long)gr * Nn + c0 + 1] = v1;
                if (Cb) {
                    __nv_bfloat162 p;
                    p.x = __float2bfloat16_rn(v0);
                    p.y = __float2bfloat16_rn(v1);
                    *reinterpret_cast<__nv_bfloat162*>(&Cb[(long)gr * Nn + c0]) = p;
                }
            }
        }
    }
}

// ============================ tf32 GEMM, N = 16 ==============================
__global__ __launch_bounds__(256) void gemm_tf32_n16_kernel(
    const float* __restrict__ A, const float* __restrict__ B,
    const float* __restrict__ bias, float* __restrict__ C,
    int M, int K)
{
    __shared__ float As[32][132];
    __shared__ float Bs[32][20];

    int tid = threadIdx.x;
    int lane = tid & 31, wid = tid >> 5;
    int g = lane >> 2, tig = lane & 3;
    int row0 = blockIdx.x * 128;

    float acc[2][4];
#pragma unroll
    for (int ni = 0; ni < 2; ni++)
#pragma unroll
        for (int q = 0; q < 4; q++) acc[ni][q] = 0.f;

    int ar = tid >> 1;
    int akc0 = (tid & 1) * 16;
    int bk = tid >> 3;
    int bn = (tid & 7) * 2;

    for (int k0 = 0; k0 < K; k0 += 32) {
        int gr = row0 + ar;
#pragma unroll
        for (int q = 0; q < 4; q++) {
            int kc = akc0 + q * 4;
            float4 v = make_float4(0.f, 0.f, 0.f, 0.f);
            if (gr < M) v = *reinterpret_cast<const float4*>(&A[(long)gr * K + k0 + kc]);
            As[kc + 0][ar] = __uint_as_float(f2tf32(v.x));
            As[kc + 1][ar] = __uint_as_float(f2tf32(v.y));
            As[kc + 2][ar] = __uint_as_float(f2tf32(v.z));
            As[kc + 3][ar] = __uint_as_float(f2tf32(v.w));
        }
        Bs[bk][bn]     = __uint_as_float(f2tf32(B[(long)(k0 + bk) * 16 + bn]));
        Bs[bk][bn + 1] = __uint_as_float(f2tf32(B[(long)(k0 + bk) * 16 + bn + 1]));
        __syncthreads();

#pragma unroll
        for (int ks = 0; ks < 32; ks += 8) {
            int mb = wid * 16 + g;
            unsigned a[4];
            a[0] = __float_as_uint(As[ks + tig][mb]);
            a[1] = __float_as_uint(As[ks + tig][mb + 8]);
            a[2] = __float_as_uint(As[ks + tig + 4][mb]);
            a[3] = __float_as_uint(As[ks + tig + 4][mb + 8]);
#pragma unroll
            for (int ni = 0; ni < 2; ni++) {
                unsigned b0 = __float_as_uint(Bs[ks + tig][ni * 8 + g]);
                unsigned b1 = __float_as_uint(Bs[ks + tig + 4][ni * 8 + g]);
                mma_tf32(acc[ni], a, b0, b1);
            }
        }
        __syncthreads();
    }

#pragma unroll
    for (int ni = 0; ni < 2; ni++) {
        int c0 = ni * 8 + 2 * tig;
#pragma unroll
        for (int half = 0; half < 2; half++) {
            int gr = row0 + wid * 16 + g + half * 8;
            if (gr >= M) continue;
            C[(long)gr * 16 + c0]     = acc[ni][half * 2 + 0] + bias[c0];
            C[(long)gr * 16 + c0 + 1] = acc[ni][half * 2 + 1] + bias[c0 + 1];
        }
    }
}

// ---------------- per-node alpha_src/alpha_dst (fp32 path) --------------------
__global__ void alpha_kernel(const float* __restrict__ asrc,
                             const float* __restrict__ adst)
{
    int w = (blockIdx.x * blockDim.x + threadIdx.x) >> 5;
    int lane = threadIdx.x & 31;
    if (w >= NNODES) return;
    float4 hv = reinterpret_cast<const float4*>(&g_h[(long)w * HF])[lane];
    float4 sa = reinterpret_cast<const float4*>(asrc)[lane];
    float4 da = reinterpret_cast<const float4*>(adst)[lane];
    float s = hv.x * sa.x + hv.y * sa.y + hv.z * sa.z + hv.w * sa.w;
    float d = hv.x * da.x + hv.y * da.y + hv.z * da.z + hv.w * da.w;
#pragma unroll
    for (int off = 8; off; off >>= 1) {
        s += __shfl_down_sync(0xffffffffu, s, off, 16);
        d += __shfl_down_sync(0xffffffffu, d, off, 16);
    }
    if ((lane & 15) == 0) {
        int hh = lane >> 4;
        g_as[w * 2 + hh] = s;
        g_ad[w * 2 + hh] = d;
    }
}

// ---------------- fused softmax + aggregation (warp per dst node) -------------
// Messages gathered from the bf16 mirror (half the L2 traffic); weights,
// accumulation, bias, output all fp32.
__global__ void agg_kernel(const float* __restrict__ bias, float* __restrict__ dst)
{
    int n = (blockIdx.x * blockDim.x + threadIdx.x) >> 5;
    int lane = threadIdx.x & 31;
    if (n >= NNODES) return;
    int beg = g_off[n], end = g_off[n + 1];
    float ad0 = g_ad[n * 2 + 0], ad1 = g_ad[n * 2 + 1];
    int head1 = lane >= 16;     // lane covers cols 4*lane..4*lane+3

    float4 acc = make_float4(0.f, 0.f, 0.f, 0.f);
    float s0 = 0.f, s1 = 0.f;

    for (int base = beg; base < end; base += 32) {
        int cnt = min(32, end - base);
        int sl = 0; float ex0 = 0.f, ex1 = 0.f;
        if (lane < cnt) {
            sl = g_csr[base + lane];
            float2 a = *reinterpret_cast<const float2*>(&g_as[sl * 2]);
            float e0 = a.x + ad0; e0 = fmaxf(e0, 0.2f * e0);
            float e1 = a.y + ad1; e1 = fmaxf(e1, 0.2f * e1);
            ex0 = __expf(e0);
            ex1 = __expf(e1);
        }
        for (int t = 0; t < cnt; t++) {
            int s    = __shfl_sync(0xffffffffu, sl, t);
            float w0 = __shfl_sync(0xffffffffu, ex0, t);
            float w1 = __shfl_sync(0xffffffffu, ex1, t);
            s0 += w0; s1 += w1;
            // 8-byte gather: 4 bf16 message values for cols 4*lane..4*lane+3
            uint2 u = reinterpret_cast<const uint2*>(&g_hb[(long)s * HF])[lane];
            __nv_bfloat162 q0 = *reinterpret_cast<__nv_bfloat162*>(&u.x);
            __nv_bfloat162 q1 = *reinterpret_cast<__nv_bfloat162*>(&u.y);
            float2 f0 = __bfloat1622float2(q0);
            float2 f1 = __bfloat1622float2(q1);
            float w = head1 ? w1 : w0;
            acc.x = fmaf(f0.x, w, acc.x);
            acc.y = fmaf(f0.y, w, acc.y);
            acc.z = fmaf(f1.x, w, acc.z);
            acc.w = fmaf(f1.y, w, acc.w);
        }
    }
    float r = head1 ? (1.f / (s1 + 1e-16f)) : (1.f / (s0 + 1e-16f));
    float4 b = reinterpret_cast<const float4*>(bias)[lane];
    float4 o;
    o.x = fmaxf(fmaf(acc.x, r, b.x), 0.f);
    o.y = fmaxf(fmaf(acc.y, r, b.y), 0.f);
    o.z = fmaxf(fmaf(acc.z, r, b.z), 0.f);
    o.w = fmaxf(fmaf(acc.w, r, b.w), 0.f);
    reinterpret_cast<float4*>(&dst[(long)n * HF])[lane] = o;
}

// ---------------- launch ------------------------------------------------------
extern "C" void kernel_launch(void* const* d_in, const int* in_sizes, int n_in,
                              void* d_out, int out_size)
{
    const float* x      = (const float*)d_in[0];
    const int*   ei     = (const int*)  d_in[1];
    const float* W1     = (const float*)d_in[2];
    const float* a_src1 = (const float*)d_in[3];
    const float* a_dst1 = (const float*)d_in[4];
    const float* b1     = (const float*)d_in[5];
    const float* W2     = (const float*)d_in[6];
    const float* a_src2 = (const float*)d_in[7];
    const float* a_dst2 = (const float*)d_in[8];
    const float* b2     = (const float*)d_in[9];
    const float* lw1    = (const float*)d_in[10];
    const float* lb1    = (const float*)d_in[11];
    const float* lw2    = (const float*)d_in[12];
    const float* lb2    = (const float*)d_in[13];
    const float* lw3    = (const float*)d_in[14];
    const float* lb3    = (const float*)d_in[15];

    int E = in_sizes[1] / 2;

    float* out    = (float*)d_out;
    float* emb    = out;                       // [N, 128]
    float* logits = out + (long)NNODES * HF;   // [N, 16]

    float *p_h, *p_h2, *p_z1, *p_z2;
    __nv_bfloat16* p_hb;
    cudaGetSymbolAddress((void**)&p_h,  g_h);
    cudaGetSymbolAddress((void**)&p_hb, g_hb);
    cudaGetSymbolAddress((void**)&p_h2, g_h2);
    cudaGetSymbolAddress((void**)&p_z1, g_z1);
    cudaGetSymbolAddress((void**)&p_z2, g_z2);

    int edgeBlocks  = cdiv(E, 256);
    int nodeBlocks  = cdiv(NNODES, 256);
    int node4Blocks = cdiv(cdiv(NNODES, 4), 256);
    int warpNodeBlk = cdiv(NNODES, 8);

    // ---------------- CSR build ----------------
    csr_zero_kernel<<<node4Blocks, 256>>>();
    csr_count_kernel<<<edgeBlocks, 256>>>(ei, E);
    csr_scan1_kernel<<<SCAN_NBLK, 1024>>>();
    csr_scan_fix_kernel<<<nodeBlocks, 256>>>();
    csr_scatter_kernel<<<edgeBlocks, 256>>>(ei, E);

    // ---------------- GAT layer 1 ----------------
    {
        dim3 grid(HF / 128, cdiv(NNODES, 128));
        gemm_tf32_kernel<<<grid, 256>>>(x, W1, nullptr, p_h, p_hb, NNODES, HF, FDIM, 0);
    }
    alpha_kernel<<<warpNodeBlk, 256>>>(a_src1, a_dst1);
    agg_kernel<<<warpNodeBlk, 256>>>(b1, p_h2);

    // ---------------- GAT layer 2 ----------------
    {
        dim3 grid(HF / 128, cdiv(NNODES, 128));
        gemm_tf32_kernel<<<grid, 256>>>(p_h2, W2, nullptr, p_h, p_hb, NNODES, HF, HF, 0);
    }
    alpha_kernel<<<warpNodeBlk, 256>>>(a_src2, a_dst2);
    agg_kernel<<<warpNodeBlk, 256>>>(b2, emb);

    // ---------------- MLP head ----------------
    {
        dim3 grid(512 / 128, cdiv(NNODES, 128));
        gemm_tf32_kernel<<<grid, 256>>>(emb, lw1, lb1, p_z1, nullptr, NNODES, 512, HF, 1);
    }
    {
        dim3 grid(256 / 128, cdiv(NNODES, 128));
        gemm_tf32_kernel<<<grid, 256>>>(p_z1, lw2, lb2, p_z2, nullptr, NNODES, 256, 512, 1);
    }
    gemm_tf32_n16_kernel<<<cdiv(NNODES, 128), 256>>>(p_z2, lw3, lb3, logits, NNODES, 256);
}